// round 17
// baseline (speedup 1.0000x reference)
#include <cuda_runtime.h>

#define BATCH 16
#define CIN   256
#define HW    4096
#define DDIM  128
#define CCL   32
#define EPSV  1e-8f
#define NF    ((long)BATCH * CIN * HW)

#define KC    32
#define NCH   8
#define NKLD  16
#define GEMM_BLKS 1024      // 16 b x 64 p-tiles (P=64 per CTA, O=256 full)

// ---- smem layout (bytes) ----
// per group: 2 stages x (A pane 128x144B = 18432  +  B pane 32x288B = 9216)
#define PANEA_SZ 18432
#define PANEB_SZ 9216
#define STAGE_SZ (PANEA_SZ + PANEB_SZ)     // 27648
#define GROUP_SZ (2 * STAGE_SZ)            // 55296
#define OFF_ZC   (2 * GROUP_SZ)            // 110592
#define OFF_BIAS (OFF_ZC + 512)            // 111104 (256 floats)
#define SMEM_TOTAL (OFF_BIAS + 1024)       // 112128 -> 2 CTAs/SM = 224.3KB

__device__ float g_kld[BATCH];
__device__ int   g_cnt;

// ---------------------------------------------------------------------------
__device__ __forceinline__ unsigned smem_u32(const void* p) {
    unsigned a;
    asm("{ .reg .u64 t; cvta.to.shared.u64 t, %1; cvt.u32.u64 %0, t; }" : "=r"(a) : "l"(p));
    return a;
}
__device__ __forceinline__ void cp16(unsigned dst, const void* src) {
    asm volatile("cp.async.cg.shared.global [%0], [%1], 16;" :: "r"(dst), "l"(src));
}
#define CP_COMMIT() asm volatile("cp.async.commit_group;")
#define CP_WAIT(n)  asm volatile("cp.async.wait_group %0;" :: "n"(n))
#define BAR_G(id)   asm volatile("bar.sync %0, 128;" :: "r"(id) : "memory")

__device__ __forceinline__ unsigned lds32(unsigned a) {
    unsigned v;
    asm volatile("ld.shared.b32 %0, [%1];" : "=r"(v) : "r"(a));
    return v;
}

__device__ __forceinline__ void mma_tf32(float* c, unsigned a0, unsigned a1,
                                         unsigned a2, unsigned a3,
                                         unsigned b0, unsigned b1) {
    asm volatile(
        "mma.sync.aligned.m16n8k8.row.col.f32.tf32.tf32.f32 "
        "{%0,%1,%2,%3}, {%4,%5,%6,%7}, {%8,%9}, {%0,%1,%2,%3};"
        : "+f"(c[0]), "+f"(c[1]), "+f"(c[2]), "+f"(c[3])
        : "r"(a0), "r"(a1), "r"(a2), "r"(a3), "r"(b0), "r"(b1));
}

// ---------------------------------------------------------------------------
// blocks 0..15: KLD.  blocks 16..1039: GEMM, O=256 x P=64 per CTA,
// two 128-thread groups (O-halves) with private pipelines + named barriers.
// ---------------------------------------------------------------------------
__global__ __launch_bounds__(256, 2)
void fused_kernel(const float* __restrict__ f,  const float* __restrict__ mu_prior,
                  const float* __restrict__ ls_prior, const float* __restrict__ pi_prior,
                  const float* __restrict__ mu_post,  const float* __restrict__ ls_post,
                  const float* __restrict__ noise_c,  const float* __restrict__ noise_z,
                  const float* __restrict__ W,        const float* __restrict__ pb,
                  float* __restrict__ out, int out_size)
{
    extern __shared__ __align__(16) char smem[];
    const int t = threadIdx.x;
    const int wid = t >> 5, lane = t & 31;

    if (blockIdx.x < NKLD) {
        // ------------------------- KLD blocks -------------------------
        const int b = blockIdx.x;
        float* S = (float*)smem;
        float* zpost = S;        float* mupo = S + 128;  float* lspo = S + 256;
        float* e2po  = S + 384;  float* kstd = S + 512;
        float* lps   = S + 640;  float* klgs = S + 896;
        if (t < DDIM) {
            float mu = mu_post[b * DDIM + t];
            float ls = ls_post[b * DDIM + t];
            float e  = expf(ls);
            mupo[t] = mu; lspo[t] = ls; e2po[t] = e * e;
            zpost[t] = mu + e * noise_c[b * DDIM + t];
            kstd[t]  = -ls + 0.5f * (e * e + mu * mu) - 0.5f;
        }
        __syncthreads();
        const int c = lane;
        {
            float lp = 0.f, klg = 0.f;
            #pragma unroll 4
            for (int j = 0; j < 16; j++) {
                int dd = wid * 16 + j;
                long idx = ((long)b * DDIM + dd) * CCL + c;
                float mpr = mu_prior[idx];
                float lpr = ls_prior[idx];
                float s2x2 = 2.f * expf(2.f * lpr);
                float dz = zpost[dd] - mpr;
                lp += -lpr - 0.91893853320467274f - dz * dz / s2x2;
                float dm = mupo[dd] - mpr;
                klg += lpr - lspo[dd] + (e2po[dd] + dm * dm) / (s2x2 + EPSV) - 0.5f;
            }
            lps[wid * 32 + c] = lp; klgs[wid * 32 + c] = klg;
        }
        __syncthreads();
        if (wid == 0) {
            float LP = 0.f, KG = 0.f;
            #pragma unroll
            for (int j = 0; j < 8; j++) { LP += lps[j * 32 + c]; KG += klgs[j * 32 + c]; }
            float m = LP;
            #pragma unroll
            for (int o = 16; o; o >>= 1) m = fmaxf(m, __shfl_xor_sync(~0u, m, o));
            float e = expf(LP - m), s = e;
            #pragma unroll
            for (int o = 16; o; o >>= 1) s += __shfl_xor_sync(~0u, s, o);
            float pi = e / s;
            float term = pi * KG + pi * (logf(pi + EPSV) - logf(pi_prior[b * CCL + c] + EPSV));
            #pragma unroll
            for (int o = 16; o; o >>= 1) term += __shfl_xor_sync(~0u, term, o);
            float ks = kstd[c] + kstd[c + 32] + kstd[c + 64] + kstd[c + 96];
            #pragma unroll
            for (int o = 16; o; o >>= 1) ks += __shfl_xor_sync(~0u, ks, o);
            if (c == 0) g_kld[b] = term + ks;
        }
        __syncthreads();
        if (t == 0) {
            __threadfence();
            int old = atomicAdd(&g_cnt, 1);
            if (old == BATCH - 1) {
                __threadfence();
                float s = 0.f;
                #pragma unroll
                for (int bb = 0; bb < BATCH; bb++) s += g_kld[bb];
                s *= (1.f / BATCH);
                for (long i = NF; i < (long)out_size; i++) out[i] = s;
                atomicExch(&g_cnt, 0);
            }
        }
        return;
    }

    // ------------------------------ GEMM blocks ------------------------------
    const int gbid = blockIdx.x - NKLD;
    const int b  = gbid >> 6;
    const int p0 = (gbid & 63) << 6;          // P=64 tile

    const int g  = t >> 7;                    // group (o-half): 0 or 1
    const int gt = t & 127;                   // thread within group
    const int wg = gt >> 5;                   // warp within group: 0..3
    const int o0 = g << 7;

    const unsigned sb = smem_u32(smem);
    const unsigned gbase = sb + g * GROUP_SZ;
    float* zc    = (float*)(smem + OFF_ZC);
    float* sbias = (float*)(smem + OFF_BIAS);

    const float* fb = f + (long)b * CIN * HW + p0;

    // group-private cp.async of chunk ch into stage st
    auto issue = [&](int ch, int st) {
        unsigned base = gbase + st * STAGE_SZ;
        #pragma unroll
        for (int j = 0; j < 8; j++) {          // A: 128 rows x 8 segs
            int id = gt + j * 128, row = id >> 3, seg = id & 7;
            cp16(base + row * 144 + seg * 16,
                 W + (long)(o0 + row) * 384 + ch * KC + seg * 4);
        }
        unsigned pbn = base + PANEA_SZ;
        #pragma unroll
        for (int j = 0; j < 4; j++) {          // B: 32 rows x 16 segs
            int id = gt + j * 128, row = id >> 4, seg = id & 15;
            cp16(pbn + row * 288 + seg * 16,
                 fb + (long)(ch * KC + row) * HW + seg * 4);
        }
        CP_COMMIT();
    };

    // ---- prologue ----
    issue(0, 0);
    issue(1, 1);
    if (t < DDIM) {
        float mu = mu_post[b * DDIM + t];
        float ls = ls_post[b * DDIM + t];
        zc[t] = mu + (expf(ls) + EPSV) * noise_z[b * DDIM + t];
    }
    __syncthreads();                  // zc visible to both groups
    {
        int o = o0 + gt;              // each group computes its own bias rows
        float acc = 0.f;
        const float* wz = W + (long)o * 384 + CIN;
        #pragma unroll
        for (int dd = 0; dd < DDIM; dd += 4) {
            float4 wv = *(const float4*)(wz + dd);
            acc += wv.x * zc[dd] + wv.y * zc[dd + 1] + wv.z * zc[dd + 2] + wv.w * zc[dd + 3];
        }
        sbias[o] = acc + pb[o];
    }
    CP_WAIT(1);                       // this thread's chunk-0 copies done
    BAR_G(1 + g);                     // publish stage0 pane + bias within group

    float c[4][4][4];
    #pragma unroll
    for (int i = 0; i < 4; i++)
        #pragma unroll
        for (int j = 0; j < 4; j++)
            #pragma unroll
            for (int k = 0; k < 4; k++) c[i][j][k] = 0.f;

    const int wy = wg >> 1;           // o block within group (64 rows): 0..1
    const int wx = wg & 1;            // p block (32 cols): 0..1
    const unsigned r = lane >> 2, qq = lane & 3;
    const unsigned abase = (wy * 64 + r) * 144 + qq * 4;
    const unsigned bbase = qq * 288 + (wx * 32 + r) * 4;

    for (int ch = 0; ch < NCH; ch++) {
        const int par = ch & 1;
        const unsigned pa  = gbase + par * STAGE_SZ;
        const unsigned pbn = pa + PANEA_SZ;

        #pragma unroll
        for (int ks = 0; ks < 4; ks++) {
            unsigned b0[4], b1[4];
            #pragma unroll
            for (int ni = 0; ni < 4; ni++) {
                unsigned ad = pbn + bbase + ks * 8 * 288 + ni * 32;
                b0[ni] = lds32(ad);
                b1[ni] = lds32(ad + 1152);     // +4 k-rows
            }
            #pragma unroll
            for (int mi = 0; mi < 4; mi++) {
                unsigned aad = pa + abase + mi * 16 * 144 + ks * 32;
                unsigned a0 = lds32(aad);
                unsigned a1 = lds32(aad + 1152);   // +8 o-rows
                unsigned a2 = lds32(aad + 16);     // +4 k
                unsigned a3 = lds32(aad + 1168);
                #pragma unroll
                for (int ni = 0; ni < 4; ni++)
                    mma_tf32(c[mi][ni], a0, a1, a2, a3, b0[ni], b1[ni]);
            }
        }

        if (ch < NCH - 1) {
            CP_WAIT(0);               // group's chunk ch+1 landed (per-thread)
            BAR_G(1 + g);             // publish ch+1; retire readers of pane[par]
            if (ch < NCH - 2) issue(ch + 2, par);
        }
    }

    // ---- epilogue: bias add + store ----
    #pragma unroll
    for (int mi = 0; mi < 4; mi++) {
        #pragma unroll
        for (int h = 0; h < 2; h++) {
            int ol = wy * 64 + mi * 16 + h * 8 + (int)r;
            float bias = sbias[o0 + ol];
            float* row = out + ((long)(b * CIN + o0 + ol)) * HW + p0 + wx * 32 + 2 * qq;
            #pragma unroll
            for (int ni = 0; ni < 4; ni++) {
                float2 v = make_float2(c[mi][ni][2 * h] + bias,
                                       c[mi][ni][2 * h + 1] + bias);
                *(float2*)(row + ni * 8) = v;
            }
        }
    }
}

// ---------------------------------------------------------------------------
extern "C" void kernel_launch(void* const* d_in, const int* in_sizes, int n_in,
                              void* d_out, int out_size)
{
    const float* f_curr   = (const float*)d_in[0];
    const float* mu_prior = (const float*)d_in[1];
    const float* ls_prior = (const float*)d_in[2];
    const float* pi_prior = (const float*)d_in[3];
    const float* mu_post  = (const float*)d_in[4];
    const float* ls_post  = (const float*)d_in[5];
    const float* noise_c  = (const float*)d_in[6];
    const float* noise_z  = (const float*)d_in[7];
    const float* W        = (const float*)d_in[8];
    const float* pb       = (const float*)d_in[9];
    float* out = (float*)d_out;

    cudaFuncSetAttribute(fused_kernel,
                         cudaFuncAttributeMaxDynamicSharedMemorySize, SMEM_TOTAL);
    fused_kernel<<<NKLD + GEMM_BLKS, 256, SMEM_TOTAL>>>(
        f_curr, mu_prior, ls_prior, pi_prior, mu_post, ls_post,
        noise_c, noise_z, W, pb, out, out_size);
}